// round 16
// baseline (speedup 1.0000x reference)
#include <cuda_runtime.h>
#include <cuda_fp16.h>
#include <math.h>
#include <math_constants.h>
#include <stdint.h>

// Problem constants
#define BSZ 2
#define TSEQ 2048
#define CDIM 1024
#define NHEAD 16
#define DHEAD 64
#define MROWS (BSZ * TSEQ)          // 4096
#define QKVCOLS (3 * CDIM)          // 3072

// ---------------------------------------------------------------------------
// Scratch
// ---------------------------------------------------------------------------
__device__ uint4 g_xf[(size_t)(MROWS / 16) * (CDIM / 16) * 32];
__device__ uint4 g_waf[(size_t)(CDIM / 16) * (QKVCOLS / 16) * 32];
__device__ uint4 g_wpf[(size_t)(CDIM / 16) * (CDIM / 16) * 32];
__device__ uint4 g_yf[(size_t)(MROWS / 16) * (CDIM / 16) * 32];
__device__ __half g_qf[(size_t)BSZ * NHEAD * TSEQ * DHEAD];   // scaled, fp16
__device__ __half g_kf[(size_t)BSZ * NHEAD * TSEQ * DHEAD];   // fp16
__device__ __half g_vt[(size_t)BSZ * NHEAD * DHEAD * TSEQ];   // [bh][d][t], fp16
__device__ float2 g_rope[TSEQ * (DHEAD / 2)];

// ---------------------------------------------------------------------------
// RoPE table
// ---------------------------------------------------------------------------
__global__ void build_rope_kernel(float2* __restrict__ table) {
    int i = blockIdx.x * blockDim.x + threadIdx.x;
    if (i >= TSEQ * 32) return;
    int t = i >> 5;
    int j = i & 31;
    double inv = pow(10000.0, -(double)j / 32.0);
    double ang = (double)t * inv;
    table[i] = make_float2((float)cos(ang), (float)sin(ang));
}

// ---------------------------------------------------------------------------
// Math helpers
// ---------------------------------------------------------------------------
__device__ __forceinline__ float ex2f(float x) {
    float r;
    asm("ex2.approx.ftz.f32 %0, %1;" : "=f"(r) : "f"(x));
    return r;
}
__device__ __forceinline__ uint32_t h2u(__half2 h) {
    return *reinterpret_cast<uint32_t*>(&h);
}
__device__ __forceinline__ void mma_f16acc(uint32_t& d0, uint32_t& d1,
                                           uint32_t a0, uint32_t a1,
                                           uint32_t a2, uint32_t a3,
                                           uint32_t b0, uint32_t b1,
                                           uint32_t c0, uint32_t c1) {
    asm volatile(
        "mma.sync.aligned.m16n8k16.row.col.f16.f16.f16.f16 "
        "{%0,%1}, {%2,%3,%4,%5}, {%6,%7}, {%8,%9};\n"
        : "=r"(d0), "=r"(d1)
        : "r"(a0), "r"(a1), "r"(a2), "r"(a3), "r"(b0), "r"(b1),
          "r"(c0), "r"(c1));
}
__device__ __forceinline__ void mma_fp16(float c[4], uint32_t a0, uint32_t a1,
                                         uint32_t a2, uint32_t a3,
                                         uint32_t b0, uint32_t b1) {
    asm volatile(
        "mma.sync.aligned.m16n8k16.row.col.f32.f16.f16.f32 "
        "{%0,%1,%2,%3}, {%4,%5,%6,%7}, {%8,%9}, {%0,%1,%2,%3};\n"
        : "+f"(c[0]), "+f"(c[1]), "+f"(c[2]), "+f"(c[3])
        : "r"(a0), "r"(a1), "r"(a2), "r"(a3), "r"(b0), "r"(b1));
}
__device__ __forceinline__ void ldsm_x4(uint32_t& r0, uint32_t& r1,
                                        uint32_t& r2, uint32_t& r3,
                                        uint32_t addr) {
    asm volatile(
        "ldmatrix.sync.aligned.m8n8.x4.shared.b16 {%0,%1,%2,%3}, [%4];"
        : "=r"(r0), "=r"(r1), "=r"(r2), "=r"(r3) : "r"(addr));
}
__device__ __forceinline__ uint32_t smem_u32(const void* p) {
    uint32_t a;
    asm("{ .reg .u64 t; cvta.to.shared.u64 t, %1; cvt.u32.u64 %0, t; }"
        : "=r"(a) : "l"(p));
    return a;
}
__device__ __forceinline__ void cp16(uint32_t smem, const void* g) {
    asm volatile("cp.async.ca.shared.global [%0], [%1], 16;"
                 :: "r"(smem), "l"(g) : "memory");
}
#define CP_COMMIT() asm volatile("cp.async.commit_group;" ::: "memory")
#define CP_WAIT0() asm volatile("cp.async.wait_group 0;" ::: "memory")
#define CP_WAIT1() asm volatile("cp.async.wait_group 1;" ::: "memory")
#define CP_WAIT2() asm volatile("cp.async.wait_group 2;" ::: "memory")

// ---------------------------------------------------------------------------
// fp16 A-fragment reorder: [M][K] -> [M/16][K/16][32]u4
// ---------------------------------------------------------------------------
__global__ void afrag16_kernel(const float* __restrict__ in,
                               uint4* __restrict__ out, int K) {
    int idx = blockIdx.x * 256 + threadIdx.x;
    int lane = idx & 31;
    int blk = idx >> 5;
    int KB = K >> 4;
    int cb = blk % KB, rb = blk / KB;
    int g = lane >> 2, tig = lane & 3;
    const float* p = in + (size_t)(rb * 16 + g) * K + cb * 16 + 2 * tig;
    const size_t r8 = (size_t)8 * K;
    uint4 v;
    v.x = h2u(__floats2half2_rn(p[0], p[1]));
    v.y = h2u(__floats2half2_rn(p[r8], p[r8 + 1]));
    v.z = h2u(__floats2half2_rn(p[8], p[9]));
    v.w = h2u(__floats2half2_rn(p[r8 + 8], p[r8 + 9]));
    out[idx] = v;
}

// ---------------------------------------------------------------------------
// fp16 paired B-fragment reorder: [K][N] -> [K/16][N/16][32]u4
// ---------------------------------------------------------------------------
__global__ void bfrag16_kernel(const float* __restrict__ in,
                               uint4* __restrict__ out, int N) {
    int idx = blockIdx.x * 256 + threadIdx.x;
    int lane = idx & 31;
    int blk = idx >> 5;
    int NB = N >> 4;
    int nbp = blk % NB, kb = blk / NB;
    int g = lane >> 2, tig = lane & 3;
    const float* p = in + (size_t)(kb * 16 + 2 * tig) * N + nbp * 16 + g;
    const size_t sN = (size_t)N;
    uint4 v;
    v.x = h2u(__floats2half2_rn(p[0], p[sN]));
    v.y = h2u(__floats2half2_rn(p[8 * sN], p[9 * sN]));
    v.z = h2u(__floats2half2_rn(p[8], p[sN + 8]));
    v.w = h2u(__floats2half2_rn(p[8 * sN + 8], p[9 * sN + 8]));
    out[idx] = v;
}

// ---------------------------------------------------------------------------
// FP16 GEMM v8: 128x64 tile, 8 warps (4m x 2n), warp tile 32x32.
// fp16-acc mma (k32 chunks -> fp32), 3-stage cp.async, 3 CTAs/SM.
// Smem: 3 x (A 8KB + B 4KB) = 36KB; mode-1 staging 128x68 fp32 = 34.8KB.
// mode 0: fp32 store + bias.  mode 1: fused RoPE/scatter QKV epilogue.
// ---------------------------------------------------------------------------
#define GEMM_SMEM_BYTES 36864
#define STG_S 68

__global__ __launch_bounds__(256, 3)
void gemm_fp16_kernel(const uint4* __restrict__ Af, const uint4* __restrict__ Bf,
                      const float* __restrict__ bias, float* __restrict__ C,
                      int M, int N, int K, int mode) {
    extern __shared__ char smg[];
    const uint32_t smb = smem_u32(smg);
    const int tid = threadIdx.x;
    const int lane = tid & 31;
    const int warp = tid >> 5;
    const int wm = warp >> 1;      // 0..3
    const int wn = warp & 1;       // 0..1
    const int g = lane >> 2;
    const int tig = lane & 3;
    const int row0 = blockIdx.y * 128;
    const int col0 = blockIdx.x * 64;
    const int KB16 = K >> 4;
    const int NB16 = N >> 4;
    const int rb0 = row0 >> 4;
    const int nbp0 = col0 >> 4;

    float acc[2][4][4];
#pragma unroll
    for (int im = 0; im < 2; im++)
#pragma unroll
        for (int in = 0; in < 4; in++)
#pragma unroll
            for (int r = 0; r < 4; r++) acc[im][in][r] = 0.0f;

    // loader maps: per stage A 512 u4 (2/thr), B 256 u4 (1/thr)
    int a_rblk[2], a_kblk[2], a_l[2];
#pragma unroll
    for (int s = 0; s < 2; s++) {
        int u = tid + s * 256;
        int ablk = u >> 5;              // 0..15 = rblk*2 + kblk
        a_rblk[s] = ablk >> 1;
        a_kblk[s] = ablk & 1;
        a_l[s] = u & 31;
    }
    const int b_kblk = tid >> 7;        // 0..1
    const int b_nbp = (tid >> 5) & 3;   // 0..3
    const int b_l = tid & 31;
    const int b_blk = tid >> 5;         // kblk*4 + nbp

    const int nT = K / 32;

#define GEMM_ISSUE(tt) do {                                                    \
        const int kbg = (tt) * 2;                                              \
        const int st = (tt) % 3;                                               \
        const uint32_t ao = (uint32_t)(st * 8192);                             \
        const uint32_t bo = 24576u + (uint32_t)(st * 4096);                    \
        _Pragma("unroll")                                                      \
        for (int s = 0; s < 2; s++) {                                          \
            cp16(smb + ao + (uint32_t)((a_rblk[s] * 2 + a_kblk[s]) * 512 + a_l[s] * 16), \
                 Af + (((size_t)(rb0 + a_rblk[s]) * KB16 + kbg + a_kblk[s]) << 5) + a_l[s]); \
        }                                                                      \
        cp16(smb + bo + (uint32_t)(b_blk * 512 + b_l * 16),                    \
             Bf + (((size_t)(kbg + b_kblk) * NB16 + nbp0 + b_nbp) << 5) + b_l);\
        CP_COMMIT();                                                           \
    } while (0)

    GEMM_ISSUE(0);
    GEMM_ISSUE(1);

    for (int t = 0; t < nT; t++) {
        if (t + 2 < nT) {
            GEMM_ISSUE(t + 2);
            CP_WAIT2();
        } else if (t + 1 < nT) {
            CP_WAIT1();
        } else {
            CP_WAIT0();
        }
        __syncthreads();

        const char* As = smg + (t % 3) * 8192;
        const char* Bs = smg + 24576 + (t % 3) * 4096;

        uint4 af[2][2];     // [kk][im]
        uint4 b4[2][2];     // [kk][p]
#pragma unroll
        for (int kk = 0; kk < 2; kk++) {
#pragma unroll
            for (int im = 0; im < 2; im++)
                af[kk][im] = *(const uint4*)(As + ((wm * 2 + im) * 2 + kk) * 512 + lane * 16);
#pragma unroll
            for (int p = 0; p < 2; p++)
                b4[kk][p] = *(const uint4*)(Bs + (kk * 4 + wn * 2 + p) * 512 + lane * 16);
        }

#pragma unroll
        for (int im = 0; im < 2; im++) {
#pragma unroll
            for (int p = 0; p < 2; p++) {
#pragma unroll
                for (int hh = 0; hh < 2; hh++) {
                    uint32_t bk0_0 = hh ? b4[0][p].z : b4[0][p].x;
                    uint32_t bk0_1 = hh ? b4[0][p].w : b4[0][p].y;
                    uint32_t bk1_0 = hh ? b4[1][p].z : b4[1][p].x;
                    uint32_t bk1_1 = hh ? b4[1][p].w : b4[1][p].y;
                    uint32_t d0, d1;
                    mma_f16acc(d0, d1, af[0][im].x, af[0][im].y, af[0][im].z,
                               af[0][im].w, bk0_0, bk0_1, 0u, 0u);
                    mma_f16acc(d0, d1, af[1][im].x, af[1][im].y, af[1][im].z,
                               af[1][im].w, bk1_0, bk1_1, d0, d1);
                    float* a4 = acc[im][2 * p + hh];
                    float2 f0 = __half22float2(*reinterpret_cast<__half2*>(&d0));
                    float2 f1 = __half22float2(*reinterpret_cast<__half2*>(&d1));
                    a4[0] += f0.x;
                    a4[1] += f0.y;
                    a4[2] += f1.x;
                    a4[3] += f1.y;
                }
            }
        }
        __syncthreads();
    }

    if (mode == 0) {
#pragma unroll
        for (int im = 0; im < 2; im++) {
            int r = row0 + wm * 32 + im * 16 + g;
#pragma unroll
            for (int in = 0; in < 4; in++) {
                int c = col0 + wn * 32 + in * 8 + tig * 2;
                float b0 = bias[c], b1 = bias[c + 1];
                float2 v0 = make_float2(acc[im][in][0] + b0, acc[im][in][1] + b1);
                float2 v1 = make_float2(acc[im][in][2] + b0, acc[im][in][3] + b1);
                *(float2*)&C[(size_t)r * N + c] = v0;
                *(float2*)&C[(size_t)(r + 8) * N + c] = v1;
            }
        }
        return;
    }

    // ---- mode 1: fused QKV epilogue (tile = one head's 64 cols) ----
    float* stg = (float*)smg;
#pragma unroll
    for (int im = 0; im < 2; im++) {
        int rl = wm * 32 + im * 16 + g;
#pragma unroll
        for (int in = 0; in < 4; in++) {
            int cl = wn * 32 + in * 8 + tig * 2;
            float b0 = bias[col0 + cl], b1 = bias[col0 + cl + 1];
            stg[rl * STG_S + cl] = acc[im][in][0] + b0;
            stg[rl * STG_S + cl + 1] = acc[im][in][1] + b1;
            stg[(rl + 8) * STG_S + cl] = acc[im][in][2] + b0;
            stg[(rl + 8) * STG_S + cl + 1] = acc[im][in][3] + b1;
        }
    }
    __syncthreads();

    const int b = row0 >> 11;
    const int tb = row0 & 2047;
    const float SCL = 0.125f * 1.4426950408889634f;

    if (col0 < 2048) {
        const bool isq = (col0 < 1024);
        __half* dst = isq ? g_qf : g_kf;
        const float scl = isq ? SCL : 1.0f;
        const int h = (col0 & 1023) >> 6;
        for (int e = tid; e < 4096; e += 256) {   // 128 rows x 32 half2
            int tl = e >> 5;
            int d = (e & 31) << 1;
            int t = tb + tl;
            float2 cs0 = g_rope[t * 32 + (d & 31)];
            float2 cs1 = g_rope[t * 32 + ((d + 1) & 31)];
            int dp = (d < 32) ? d + 32 : d - 32;
            float sgn = (d < 32) ? -1.0f : 1.0f;
            float v0 = stg[tl * STG_S + d];
            float v1 = stg[tl * STG_S + d + 1];
            float p0 = stg[tl * STG_S + dp];
            float p1 = stg[tl * STG_S + dp + 1];
            float q0 = (v0 * cs0.x + sgn * p0 * cs0.y) * scl;
            float q1 = (v1 * cs1.x + sgn * p1 * cs1.y) * scl;
            *(__half2*)&dst[(((size_t)(b * NHEAD + h)) * TSEQ + t) * DHEAD + d] =
                __floats2half2_rn(q0, q1);
        }
    } else {
        const int h = (col0 - 2048) >> 6;
        for (int e = tid; e < 4096; e += 256) {   // 64 d x 64 half2-of-t
            int d = e >> 6;
            int t2 = (e & 63) << 1;
            float v0 = stg[t2 * STG_S + d];
            float v1 = stg[(t2 + 1) * STG_S + d];
            *(__half2*)&g_vt[(((size_t)(b * NHEAD + h)) * DHEAD + d) * TSEQ + tb + t2] =
                __floats2half2_rn(v0, v1);
        }
    }
#undef GEMM_ISSUE
}

// ---------------------------------------------------------------------------
// Flash attention v8 (unchanged): S + PV single fp16 mma (f32 acc),
// fp16 A-frag epilogue for y.
// ---------------------------------------------------------------------------
#define FRS 144
#define OFF_K 0
#define OFF_VT 9216
#define BUFB 18432
#define FLASH_SMEM_BYTES (2 * BUFB)

#define NEGBIG (-1e30f)

__global__ __launch_bounds__(128, 3)
void flash_mma_kernel(const __half* __restrict__ QF,
                      const __half* __restrict__ KF,
                      const __half* __restrict__ VT) {
    extern __shared__ char smc[];
    const uint32_t smb = smem_u32(smc);

    int bh = blockIdx.y;
    int qt = gridDim.x - 1 - blockIdx.x;
    int q0 = qt * 64;

    int tid = threadIdx.x;
    int lane = tid & 31;
    int w = tid >> 5;
    int g = lane >> 2;
    int tig = lane & 3;
    const int r0 = w * 16 + g;

    const int jj = lane & 7;
    const uint32_t ldsm_base =
        (uint32_t)((jj + ((lane >> 4) & 1) * 8) * FRS + ((lane >> 3) & 1) * 16);

    const __half* KFg = KF + (size_t)bh * TSEQ * DHEAD;
    const __half* VTg = VT + (size_t)bh * DHEAD * TSEQ;

    {
#pragma unroll
        for (int s = 0; s < 4; s++) {
            int f = tid + s * 128;
            int r = f >> 3;
            int c = (f & 7) * 8;
            uint32_t ro = (uint32_t)(r * FRS + c * 2);
            cp16(smb + OFF_K + ro, KFg + (size_t)r * DHEAD + c);
            cp16(smb + OFF_VT + ro, VTg + (size_t)r * TSEQ + c);
        }
        CP_COMMIT();
    }

    uint32_t qa[4][4];
    {
        const __half* Qg = QF + ((size_t)bh * TSEQ + q0 + r0) * DHEAD;
#pragma unroll
        for (int ks = 0; ks < 4; ks++) {
            int c0 = ks * 16 + 2 * tig;
            qa[ks][0] = *(const uint32_t*)(Qg + c0);
            qa[ks][1] = *(const uint32_t*)(Qg + 8 * DHEAD + c0);
            qa[ks][2] = *(const uint32_t*)(Qg + c0 + 8);
            qa[ks][3] = *(const uint32_t*)(Qg + 8 * DHEAD + c0 + 8);
        }
    }

    float oacc[8][4];
#pragma unroll
    for (int db = 0; db < 8; db++)
#pragma unroll
        for (int r = 0; r < 4; r++) oacc[db][r] = 0.0f;
    float m0 = NEGBIG, m1 = NEGBIG, l0 = 0.0f, l1 = 0.0f;

    for (int jt = 0; jt <= qt; jt++) {
        CP_WAIT0();
        __syncthreads();

        if (jt < qt) {
            int k0n = (jt + 1) * 64;
            uint32_t nb_ = smb + ((jt + 1) & 1) * BUFB;
#pragma unroll
            for (int s = 0; s < 4; s++) {
                int f = tid + s * 128;
                int r = f >> 3;
                int c = (f & 7) * 8;
                uint32_t ro = (uint32_t)(r * FRS + c * 2);
                cp16(nb_ + OFF_K + ro, KFg + (size_t)(k0n + r) * DHEAD + c);
                cp16(nb_ + OFF_VT + ro, VTg + (size_t)r * TSEQ + k0n + c);
            }
            CP_COMMIT();
        }

        const uint32_t bufa = smb + (jt & 1) * BUFB + ldsm_base;

        float sacc[8][4];
#pragma unroll
        for (int nb = 0; nb < 8; nb++)
#pragma unroll
            for (int r = 0; r < 4; r++) sacc[nb][r] = 0.0f;

#pragma unroll
        for (int ks = 0; ks < 4; ks++) {
            const uint32_t ko = (uint32_t)(ks * 32);
#pragma unroll
            for (int nbp = 0; nbp < 4; nbp++) {
                const uint32_t ba = bufa + (uint32_t)(nbp * 16 * FRS) + ko;
                uint32_t b0, b1, b2, b3;
                ldsm_x4(b0, b1, b2, b3, ba + OFF_K);
                mma_fp16(sacc[2 * nbp], qa[ks][0], qa[ks][1], qa[ks][2], qa[ks][3], b0, b1);
                mma_fp16(sacc[2 * nbp + 1], qa[ks][0], qa[ks][1], qa[ks][2], qa[ks][3], b2, b3);
            }
        }

        if (jt == qt) {
#pragma unroll
            for (int nb = 0; nb < 8; nb++) {
                int c0 = nb * 8 + 2 * tig;
#pragma unroll
                for (int e = 0; e < 2; e++) {
                    if (c0 + e > r0) sacc[nb][e] = NEGBIG;
                    if (c0 + e > r0 + 8) sacc[nb][2 + e] = NEGBIG;
                }
            }
        }

        float tm0 = NEGBIG, tm1 = NEGBIG;
#pragma unroll
        for (int nb = 0; nb < 8; nb++) {
            tm0 = fmaxf(tm0, fmaxf(sacc[nb][0], sacc[nb][1]));
            tm1 = fmaxf(tm1, fmaxf(sacc[nb][2], sacc[nb][3]));
        }
        tm0 = fmaxf(tm0, __shfl_xor_sync(0xffffffffu, tm0, 1));
        tm0 = fmaxf(tm0, __shfl_xor_sync(0xffffffffu, tm0, 2));
        tm1 = fmaxf(tm1, __shfl_xor_sync(0xffffffffu, tm1, 1));
        tm1 = fmaxf(tm1, __shfl_xor_sync(0xffffffffu, tm1, 2));

        float mn0 = fmaxf(m0, tm0);
        float mn1 = fmaxf(m1, tm1);
        float corr0 = ex2f(m0 - mn0);
        float corr1 = ex2f(m1 - mn1);
        float rs0 = 0.0f, rs1 = 0.0f;
#pragma unroll
        for (int nb = 0; nb < 8; nb++) {
            sacc[nb][0] = ex2f(sacc[nb][0] - mn0);
            sacc[nb][1] = ex2f(sacc[nb][1] - mn0);
            sacc[nb][2] = ex2f(sacc[nb][2] - mn1);
            sacc[nb][3] = ex2f(sacc[nb][3] - mn1);
            rs0 += sacc[nb][0] + sacc[nb][1];
            rs1 += sacc[nb][2] + sacc[nb][3];
        }
        rs0 += __shfl_xor_sync(0xffffffffu, rs0, 1);
        rs0 += __shfl_xor_sync(0xffffffffu, rs0, 2);
        rs1 += __shfl_xor_sync(0xffffffffu, rs1, 1);
        rs1 += __shfl_xor_sync(0xffffffffu, rs1, 2);

        l0 = l0 * corr0 + rs0;
        l1 = l1 * corr1 + rs1;
        m0 = mn0;
        m1 = mn1;
#pragma unroll
        for (int db = 0; db < 8; db++) {
            oacc[db][0] *= corr0;
            oacc[db][1] *= corr0;
            oacc[db][2] *= corr1;
            oacc[db][3] *= corr1;
        }

#pragma unroll
        for (int ks = 0; ks < 4; ks++) {
            uint32_t p16[4];
            p16[0] = h2u(__floats2half2_rn(sacc[2 * ks][0], sacc[2 * ks][1]));
            p16[1] = h2u(__floats2half2_rn(sacc[2 * ks][2], sacc[2 * ks][3]));
            p16[2] = h2u(__floats2half2_rn(sacc[2 * ks + 1][0], sacc[2 * ks + 1][1]));
            p16[3] = h2u(__floats2half2_rn(sacc[2 * ks + 1][2], sacc[2 * ks + 1][3]));
            const uint32_t ko = (uint32_t)(ks * 32);
#pragma unroll
            for (int dbp = 0; dbp < 4; dbp++) {
                const uint32_t ba = bufa + (uint32_t)(dbp * 16 * FRS) + ko;
                uint32_t v0, v1, v2, v3;
                ldsm_x4(v0, v1, v2, v3, ba + OFF_VT);
                mma_fp16(oacc[2 * dbp], p16[0], p16[1], p16[2], p16[3], v0, v1);
                mma_fp16(oacc[2 * dbp + 1], p16[0], p16[1], p16[2], p16[3], v2, v3);
            }
        }
    }

    float inv0 = 1.0f / l0;
    float inv1 = 1.0f / l1;
    int b = bh >> 4;
    int h = bh & 15;
    const size_t rb = (size_t)((b * TSEQ + q0) >> 4) + w;
#pragma unroll
    for (int dbp = 0; dbp < 4; dbp++) {
        int cb = h * 4 + dbp;
        uint4 v;
        v.x = h2u(__floats2half2_rn(oacc[2 * dbp][0] * inv0, oacc[2 * dbp][1] * inv0));
        v.y = h2u(__floats2half2_rn(oacc[2 * dbp][2] * inv1, oacc[2 * dbp][3] * inv1));
        v.z = h2u(__floats2half2_rn(oacc[2 * dbp + 1][0] * inv0, oacc[2 * dbp + 1][1] * inv0));
        v.w = h2u(__floats2half2_rn(oacc[2 * dbp + 1][2] * inv1, oacc[2 * dbp + 1][3] * inv1));
        g_yf[(rb * 64 + cb) * 32 + lane] = v;
    }
}

// ---------------------------------------------------------------------------
// Launch
// ---------------------------------------------------------------------------
extern "C" void kernel_launch(void* const* d_in, const int* in_sizes, int n_in,
                              void* d_out, int out_size) {
    const float* x      = (const float*)d_in[0];
    const float* w_attn = (const float*)d_in[1];
    const float* b_attn = (const float*)d_in[2];
    const float* w_proj = (const float*)d_in[3];
    const float* b_proj = (const float*)d_in[4];
    float* out = (float*)d_out;

    uint4 *xf, *waf, *wpf, *yf;
    float2* rope;
    __half *qf, *kf, *vt;
    cudaGetSymbolAddress((void**)&xf, g_xf);
    cudaGetSymbolAddress((void**)&waf, g_waf);
    cudaGetSymbolAddress((void**)&wpf, g_wpf);
    cudaGetSymbolAddress((void**)&yf, g_yf);
    cudaGetSymbolAddress((void**)&qf, g_qf);
    cudaGetSymbolAddress((void**)&kf, g_kf);
    cudaGetSymbolAddress((void**)&vt, g_vt);
    cudaGetSymbolAddress((void**)&rope, g_rope);

    cudaFuncSetAttribute(gemm_fp16_kernel,
                         cudaFuncAttributeMaxDynamicSharedMemorySize,
                         GEMM_SMEM_BYTES);
    cudaFuncSetAttribute(flash_mma_kernel,
                         cudaFuncAttributeMaxDynamicSharedMemorySize,
                         FLASH_SMEM_BYTES);

    build_rope_kernel<<<(TSEQ * 32 + 255) / 256, 256>>>(rope);

    afrag16_kernel<<<(MROWS / 16) * (CDIM / 16) * 32 / 256, 256>>>(x, xf, CDIM);
    bfrag16_kernel<<<(CDIM / 16) * (QKVCOLS / 16) * 32 / 256, 256>>>(w_attn, waf, QKVCOLS);
    bfrag16_kernel<<<(CDIM / 16) * (CDIM / 16) * 32 / 256, 256>>>(w_proj, wpf, CDIM);

    // QKV GEMM with fused RoPE/scatter epilogue (tiles 128x64)
    gemm_fp16_kernel<<<dim3(QKVCOLS / 64, MROWS / 128), 256, GEMM_SMEM_BYTES>>>(
        xf, waf, b_attn, out /*unused*/, MROWS, QKVCOLS, CDIM, 1);

    // Flash attention (writes yf as fp16 A-fragments)
    flash_mma_kernel<<<dim3(TSEQ / 64, BSZ * NHEAD), 128, FLASH_SMEM_BYTES>>>(
        qf, kf, vt);

    // Output projection (tiles 128x64)
    gemm_fp16_kernel<<<dim3(CDIM / 64, MROWS / 128), 256, GEMM_SMEM_BYTES>>>(
        yf, wpf, b_proj, out, MROWS, CDIM, CDIM, 0);
}

// round 17
// speedup vs baseline: 1.0300x; 1.0300x over previous
#include <cuda_runtime.h>
#include <cuda_fp16.h>
#include <math.h>
#include <math_constants.h>
#include <stdint.h>

// Problem constants
#define BSZ 2
#define TSEQ 2048
#define CDIM 1024
#define NHEAD 16
#define DHEAD 64
#define MROWS (BSZ * TSEQ)          // 4096
#define QKVCOLS (3 * CDIM)          // 3072

// ---------------------------------------------------------------------------
// Scratch
// ---------------------------------------------------------------------------
__device__ uint4 g_xf[(size_t)(MROWS / 16) * (CDIM / 16) * 32];
__device__ uint4 g_waf[(size_t)(CDIM / 16) * (QKVCOLS / 16) * 32];
__device__ uint4 g_wpf[(size_t)(CDIM / 16) * (CDIM / 16) * 32];
__device__ uint4 g_yf[(size_t)(MROWS / 16) * (CDIM / 16) * 32];
__device__ __half g_qf[(size_t)BSZ * NHEAD * TSEQ * DHEAD];   // scaled, fp16
__device__ __half g_kf[(size_t)BSZ * NHEAD * TSEQ * DHEAD];   // fp16
__device__ __half g_vt[(size_t)BSZ * NHEAD * DHEAD * TSEQ];   // [bh][d][t], fp16
__device__ float2 g_rope[TSEQ * (DHEAD / 2)];

// ---------------------------------------------------------------------------
// RoPE table
// ---------------------------------------------------------------------------
__global__ void build_rope_kernel(float2* __restrict__ table) {
    int i = blockIdx.x * blockDim.x + threadIdx.x;
    if (i >= TSEQ * 32) return;
    int t = i >> 5;
    int j = i & 31;
    double inv = pow(10000.0, -(double)j / 32.0);
    double ang = (double)t * inv;
    table[i] = make_float2((float)cos(ang), (float)sin(ang));
}

// ---------------------------------------------------------------------------
// Math helpers
// ---------------------------------------------------------------------------
__device__ __forceinline__ float ex2f(float x) {
    float r;
    asm("ex2.approx.ftz.f32 %0, %1;" : "=f"(r) : "f"(x));
    return r;
}
__device__ __forceinline__ uint32_t h2u(__half2 h) {
    return *reinterpret_cast<uint32_t*>(&h);
}
__device__ __forceinline__ void mma_f16acc(uint32_t& d0, uint32_t& d1,
                                           uint32_t a0, uint32_t a1,
                                           uint32_t a2, uint32_t a3,
                                           uint32_t b0, uint32_t b1,
                                           uint32_t c0, uint32_t c1) {
    asm volatile(
        "mma.sync.aligned.m16n8k16.row.col.f16.f16.f16.f16 "
        "{%0,%1}, {%2,%3,%4,%5}, {%6,%7}, {%8,%9};\n"
        : "=r"(d0), "=r"(d1)
        : "r"(a0), "r"(a1), "r"(a2), "r"(a3), "r"(b0), "r"(b1),
          "r"(c0), "r"(c1));
}
__device__ __forceinline__ void mma_fp16(float c[4], uint32_t a0, uint32_t a1,
                                         uint32_t a2, uint32_t a3,
                                         uint32_t b0, uint32_t b1) {
    asm volatile(
        "mma.sync.aligned.m16n8k16.row.col.f32.f16.f16.f32 "
        "{%0,%1,%2,%3}, {%4,%5,%6,%7}, {%8,%9}, {%0,%1,%2,%3};\n"
        : "+f"(c[0]), "+f"(c[1]), "+f"(c[2]), "+f"(c[3])
        : "r"(a0), "r"(a1), "r"(a2), "r"(a3), "r"(b0), "r"(b1));
}
__device__ __forceinline__ void ldsm_x4(uint32_t& r0, uint32_t& r1,
                                        uint32_t& r2, uint32_t& r3,
                                        uint32_t addr) {
    asm volatile(
        "ldmatrix.sync.aligned.m8n8.x4.shared.b16 {%0,%1,%2,%3}, [%4];"
        : "=r"(r0), "=r"(r1), "=r"(r2), "=r"(r3) : "r"(addr));
}
__device__ __forceinline__ uint32_t smem_u32(const void* p) {
    uint32_t a;
    asm("{ .reg .u64 t; cvta.to.shared.u64 t, %1; cvt.u32.u64 %0, t; }"
        : "=r"(a) : "l"(p));
    return a;
}
__device__ __forceinline__ void cp16(uint32_t smem, const void* g) {
    asm volatile("cp.async.ca.shared.global [%0], [%1], 16;"
                 :: "r"(smem), "l"(g) : "memory");
}
#define CP_COMMIT() asm volatile("cp.async.commit_group;" ::: "memory")
#define CP_WAIT0() asm volatile("cp.async.wait_group 0;" ::: "memory")
#define CP_WAIT1() asm volatile("cp.async.wait_group 1;" ::: "memory")
#define CP_WAIT2() asm volatile("cp.async.wait_group 2;" ::: "memory")

// ---------------------------------------------------------------------------
// fp16 A-fragment reorder: [M][K] -> [M/16][K/16][32]u4
// ---------------------------------------------------------------------------
__global__ void afrag16_kernel(const float* __restrict__ in,
                               uint4* __restrict__ out, int K) {
    int idx = blockIdx.x * 256 + threadIdx.x;
    int lane = idx & 31;
    int blk = idx >> 5;
    int KB = K >> 4;
    int cb = blk % KB, rb = blk / KB;
    int g = lane >> 2, tig = lane & 3;
    const float* p = in + (size_t)(rb * 16 + g) * K + cb * 16 + 2 * tig;
    const size_t r8 = (size_t)8 * K;
    uint4 v;
    v.x = h2u(__floats2half2_rn(p[0], p[1]));
    v.y = h2u(__floats2half2_rn(p[r8], p[r8 + 1]));
    v.z = h2u(__floats2half2_rn(p[8], p[9]));
    v.w = h2u(__floats2half2_rn(p[r8 + 8], p[r8 + 9]));
    out[idx] = v;
}

// ---------------------------------------------------------------------------
// fp16 paired B-fragment reorder: [K][N] -> [K/16][N/16][32]u4
// ---------------------------------------------------------------------------
__global__ void bfrag16_kernel(const float* __restrict__ in,
                               uint4* __restrict__ out, int N) {
    int idx = blockIdx.x * 256 + threadIdx.x;
    int lane = idx & 31;
    int blk = idx >> 5;
    int NB = N >> 4;
    int nbp = blk % NB, kb = blk / NB;
    int g = lane >> 2, tig = lane & 3;
    const float* p = in + (size_t)(kb * 16 + 2 * tig) * N + nbp * 16 + g;
    const size_t sN = (size_t)N;
    uint4 v;
    v.x = h2u(__floats2half2_rn(p[0], p[sN]));
    v.y = h2u(__floats2half2_rn(p[8 * sN], p[9 * sN]));
    v.z = h2u(__floats2half2_rn(p[8], p[sN + 8]));
    v.w = h2u(__floats2half2_rn(p[8 * sN + 8], p[9 * sN + 8]));
    out[idx] = v;
}

// ---------------------------------------------------------------------------
// FP16 GEMM v9: persistent 128x128 tiles, fp16-acc mma (k32 chunks -> fp32),
// 3-stage cp.async.  grid = min(nTiles, 296); CTA loops tiles bid+=gridDim.
// mode 0: fp32 store + bias.  mode 1: fused RoPE/scatter QKV epilogue.
// Smem: pipeline 48KB; mode-1 staging 128x133 fp32 = 68096 B (reused).
// ---------------------------------------------------------------------------
#define GEMM_SMEM_BYTES 68096
#define STG_S 133

__global__ __launch_bounds__(256, 2)
void gemm_fp16_kernel(const uint4* __restrict__ Af, const uint4* __restrict__ Bf,
                      const float* __restrict__ bias, float* __restrict__ C,
                      int M, int N, int K, int mode) {
    extern __shared__ char smg[];
    const uint32_t smb = smem_u32(smg);
    const int tid = threadIdx.x;
    const int lane = tid & 31;
    const int warp = tid >> 5;
    const int wm = warp >> 2;
    const int wn = warp & 3;
    const int g = lane >> 2;
    const int tig = lane & 3;
    const int KB16 = K >> 4;
    const int NB16 = N >> 4;
    const int ntn = N >> 7;            // tiles across N
    const int nTiles = (M >> 7) * ntn;
    const int nT = K / 32;

    int a_rblk[2], a_kblk[2], a_l[2];
    int b_blk[2], b_kblk[2], b_nbp[2], b_l[2];
#pragma unroll
    for (int s = 0; s < 2; s++) {
        int u = tid + s * 256;
        int ablk = u >> 5;
        a_rblk[s] = ablk >> 1;
        a_kblk[s] = ablk & 1;
        a_l[s] = u & 31;
        b_blk[s] = u >> 5;
        b_kblk[s] = u >> 8;
        b_nbp[s] = (u >> 5) & 7;
        b_l[s] = u & 31;
    }

    for (int tile = blockIdx.x; tile < nTiles; tile += gridDim.x) {
        const int row0 = (tile / ntn) << 7;
        const int col0 = (tile % ntn) << 7;
        const int rb0 = row0 >> 4;
        const int nbp0 = col0 >> 4;

        float acc[4][4][4];
#pragma unroll
        for (int im = 0; im < 4; im++)
#pragma unroll
            for (int in = 0; in < 4; in++)
#pragma unroll
                for (int r = 0; r < 4; r++) acc[im][in][r] = 0.0f;

#define GEMM_ISSUE(tt) do {                                                    \
        const int kbg = (tt) * 2;                                              \
        const int st = (tt) % 3;                                               \
        const uint32_t ao = (uint32_t)(st * 8192);                             \
        const uint32_t bo = 24576u + (uint32_t)(st * 8192);                    \
        _Pragma("unroll")                                                      \
        for (int s = 0; s < 2; s++) {                                          \
            cp16(smb + ao + (uint32_t)((a_rblk[s] * 2 + a_kblk[s]) * 512 + a_l[s] * 16), \
                 Af + (((size_t)(rb0 + a_rblk[s]) * KB16 + kbg + a_kblk[s]) << 5) + a_l[s]); \
            cp16(smb + bo + (uint32_t)(b_blk[s] * 512 + b_l[s] * 16),          \
                 Bf + (((size_t)(kbg + b_kblk[s]) * NB16 + nbp0 + b_nbp[s]) << 5) + b_l[s]); \
        }                                                                      \
        CP_COMMIT();                                                           \
    } while (0)

        GEMM_ISSUE(0);
        GEMM_ISSUE(1);

        for (int t = 0; t < nT; t++) {
            if (t + 2 < nT) {
                GEMM_ISSUE(t + 2);
                CP_WAIT2();
            } else if (t + 1 < nT) {
                CP_WAIT1();
            } else {
                CP_WAIT0();
            }
            __syncthreads();

            const char* As = smg + (t % 3) * 8192;
            const char* Bs = smg + 24576 + (t % 3) * 8192;

            uint4 af[2][4];
            uint4 b4[2][2];
#pragma unroll
            for (int kk = 0; kk < 2; kk++) {
#pragma unroll
                for (int im = 0; im < 4; im++)
                    af[kk][im] = *(const uint4*)(As + ((wm * 4 + im) * 2 + kk) * 512 + lane * 16);
#pragma unroll
                for (int p = 0; p < 2; p++)
                    b4[kk][p] = *(const uint4*)(Bs + (kk * 8 + wn * 2 + p) * 512 + lane * 16);
            }

#pragma unroll
            for (int im = 0; im < 4; im++) {
#pragma unroll
                for (int p = 0; p < 2; p++) {
#pragma unroll
                    for (int hh = 0; hh < 2; hh++) {
                        uint32_t bk0_0 = hh ? b4[0][p].z : b4[0][p].x;
                        uint32_t bk0_1 = hh ? b4[0][p].w : b4[0][p].y;
                        uint32_t bk1_0 = hh ? b4[1][p].z : b4[1][p].x;
                        uint32_t bk1_1 = hh ? b4[1][p].w : b4[1][p].y;
                        uint32_t d0, d1;
                        mma_f16acc(d0, d1, af[0][im].x, af[0][im].y, af[0][im].z,
                                   af[0][im].w, bk0_0, bk0_1, 0u, 0u);
                        mma_f16acc(d0, d1, af[1][im].x, af[1][im].y, af[1][im].z,
                                   af[1][im].w, bk1_0, bk1_1, d0, d1);
                        float* a4 = acc[im][2 * p + hh];
                        float2 f0 = __half22float2(*reinterpret_cast<__half2*>(&d0));
                        float2 f1 = __half22float2(*reinterpret_cast<__half2*>(&d1));
                        a4[0] += f0.x;
                        a4[1] += f0.y;
                        a4[2] += f1.x;
                        a4[3] += f1.y;
                    }
                }
            }
            __syncthreads();
        }

        if (mode == 0) {
#pragma unroll
            for (int im = 0; im < 4; im++) {
                int r = row0 + wm * 64 + im * 16 + g;
#pragma unroll
                for (int in = 0; in < 4; in++) {
                    int c = col0 + wn * 32 + in * 8 + tig * 2;
                    float b0 = bias[c], b1 = bias[c + 1];
                    float2 v0 = make_float2(acc[im][in][0] + b0, acc[im][in][1] + b1);
                    float2 v1 = make_float2(acc[im][in][2] + b0, acc[im][in][3] + b1);
                    *(float2*)&C[(size_t)r * N + c] = v0;
                    *(float2*)&C[(size_t)(r + 8) * N + c] = v1;
                }
            }
            continue;
        }

        // ---- mode 1: fused QKV epilogue ----
        float* stg = (float*)smg;
#pragma unroll
        for (int im = 0; im < 4; im++) {
            int rl = wm * 64 + im * 16 + g;
#pragma unroll
            for (int in = 0; in < 4; in++) {
                int cl = wn * 32 + in * 8 + tig * 2;
                float b0 = bias[col0 + cl], b1 = bias[col0 + cl + 1];
                stg[rl * STG_S + cl] = acc[im][in][0] + b0;
                stg[rl * STG_S + cl + 1] = acc[im][in][1] + b1;
                stg[(rl + 8) * STG_S + cl] = acc[im][in][2] + b0;
                stg[(rl + 8) * STG_S + cl + 1] = acc[im][in][3] + b1;
            }
        }
        __syncthreads();

        const int b = row0 >> 11;
        const int tb = row0 & 2047;
        const float SCL = 0.125f * 1.4426950408889634f;

        if (col0 < 2048) {
            const bool isq = (col0 < 1024);
            __half* dst = isq ? g_qf : g_kf;
            const float scl = isq ? SCL : 1.0f;
            const int cbase = col0 & 1023;
            for (int e = tid; e < 8192; e += 256) {
                int tl = e >> 6;
                int c2 = (e & 63) << 1;
                int colg = cbase + c2;
                int h = colg >> 6;
                int d = colg & 63;
                int t = tb + tl;
                float2 cs0 = g_rope[t * 32 + (d & 31)];
                float2 cs1 = g_rope[t * 32 + ((d + 1) & 31)];
                int cp = (d < 32) ? c2 + 32 : c2 - 32;
                float sgn = (d < 32) ? -1.0f : 1.0f;
                float v0 = stg[tl * STG_S + c2];
                float v1 = stg[tl * STG_S + c2 + 1];
                float p0 = stg[tl * STG_S + cp];
                float p1 = stg[tl * STG_S + cp + 1];
                float q0 = (v0 * cs0.x + sgn * p0 * cs0.y) * scl;
                float q1 = (v1 * cs1.x + sgn * p1 * cs1.y) * scl;
                *(__half2*)&dst[(((size_t)(b * NHEAD + h)) * TSEQ + t) * DHEAD + d] =
                    __floats2half2_rn(q0, q1);
            }
        } else {
            const int cbase = col0 - 2048;
            for (int e = tid; e < 8192; e += 256) {
                int dl = e >> 6;
                int t2 = (e & 63) << 1;
                int colg = cbase + dl;
                int h = colg >> 6;
                int d = colg & 63;
                float v0 = stg[t2 * STG_S + dl];
                float v1 = stg[(t2 + 1) * STG_S + dl];
                *(__half2*)&g_vt[(((size_t)(b * NHEAD + h)) * DHEAD + d) * TSEQ + tb + t2] =
                    __floats2half2_rn(v0, v1);
            }
        }
        __syncthreads();   // staging reused by next tile's pipeline
#undef GEMM_ISSUE
    }
}

// ---------------------------------------------------------------------------
// Flash attention v8 (unchanged): S + PV single fp16 mma (f32 acc),
// fp16 A-frag epilogue for y.
// ---------------------------------------------------------------------------
#define FRS 144
#define OFF_K 0
#define OFF_VT 9216
#define BUFB 18432
#define FLASH_SMEM_BYTES (2 * BUFB)

#define NEGBIG (-1e30f)

__global__ __launch_bounds__(128, 3)
void flash_mma_kernel(const __half* __restrict__ QF,
                      const __half* __restrict__ KF,
                      const __half* __restrict__ VT) {
    extern __shared__ char smc[];
    const uint32_t smb = smem_u32(smc);

    int bh = blockIdx.y;
    int qt = gridDim.x - 1 - blockIdx.x;
    int q0 = qt * 64;

    int tid = threadIdx.x;
    int lane = tid & 31;
    int w = tid >> 5;
    int g = lane >> 2;
    int tig = lane & 3;
    const int r0 = w * 16 + g;

    const int jj = lane & 7;
    const uint32_t ldsm_base =
        (uint32_t)((jj + ((lane >> 4) & 1) * 8) * FRS + ((lane >> 3) & 1) * 16);

    const __half* KFg = KF + (size_t)bh * TSEQ * DHEAD;
    const __half* VTg = VT + (size_t)bh * DHEAD * TSEQ;

    {
#pragma unroll
        for (int s = 0; s < 4; s++) {
            int f = tid + s * 128;
            int r = f >> 3;
            int c = (f & 7) * 8;
            uint32_t ro = (uint32_t)(r * FRS + c * 2);
            cp16(smb + OFF_K + ro, KFg + (size_t)r * DHEAD + c);
            cp16(smb + OFF_VT + ro, VTg + (size_t)r * TSEQ + c);
        }
        CP_COMMIT();
    }

    uint32_t qa[4][4];
    {
        const __half* Qg = QF + ((size_t)bh * TSEQ + q0 + r0) * DHEAD;
#pragma unroll
        for (int ks = 0; ks < 4; ks++) {
            int c0 = ks * 16 + 2 * tig;
            qa[ks][0] = *(const uint32_t*)(Qg + c0);
            qa[ks][1] = *(const uint32_t*)(Qg + 8 * DHEAD + c0);
            qa[ks][2] = *(const uint32_t*)(Qg + c0 + 8);
            qa[ks][3] = *(const uint32_t*)(Qg + 8 * DHEAD + c0 + 8);
        }
    }

    float oacc[8][4];
#pragma unroll
    for (int db = 0; db < 8; db++)
#pragma unroll
        for (int r = 0; r < 4; r++) oacc[db][r] = 0.0f;
    float m0 = NEGBIG, m1 = NEGBIG, l0 = 0.0f, l1 = 0.0f;

    for (int jt = 0; jt <= qt; jt++) {
        CP_WAIT0();
        __syncthreads();

        if (jt < qt) {
            int k0n = (jt + 1) * 64;
            uint32_t nb_ = smb + ((jt + 1) & 1) * BUFB;
#pragma unroll
            for (int s = 0; s < 4; s++) {
                int f = tid + s * 128;
                int r = f >> 3;
                int c = (f & 7) * 8;
                uint32_t ro = (uint32_t)(r * FRS + c * 2);
                cp16(nb_ + OFF_K + ro, KFg + (size_t)(k0n + r) * DHEAD + c);
                cp16(nb_ + OFF_VT + ro, VTg + (size_t)r * TSEQ + k0n + c);
            }
            CP_COMMIT();
        }

        const uint32_t bufa = smb + (jt & 1) * BUFB + ldsm_base;

        float sacc[8][4];
#pragma unroll
        for (int nb = 0; nb < 8; nb++)
#pragma unroll
            for (int r = 0; r < 4; r++) sacc[nb][r] = 0.0f;

#pragma unroll
        for (int ks = 0; ks < 4; ks++) {
            const uint32_t ko = (uint32_t)(ks * 32);
#pragma unroll
            for (int nbp = 0; nbp < 4; nbp++) {
                const uint32_t ba = bufa + (uint32_t)(nbp * 16 * FRS) + ko;
                uint32_t b0, b1, b2, b3;
                ldsm_x4(b0, b1, b2, b3, ba + OFF_K);
                mma_fp16(sacc[2 * nbp], qa[ks][0], qa[ks][1], qa[ks][2], qa[ks][3], b0, b1);
                mma_fp16(sacc[2 * nbp + 1], qa[ks][0], qa[ks][1], qa[ks][2], qa[ks][3], b2, b3);
            }
        }

        if (jt == qt) {
#pragma unroll
            for (int nb = 0; nb < 8; nb++) {
                int c0 = nb * 8 + 2 * tig;
#pragma unroll
                for (int e = 0; e < 2; e++) {
                    if (c0 + e > r0) sacc[nb][e] = NEGBIG;
                    if (c0 + e > r0 + 8) sacc[nb][2 + e] = NEGBIG;
                }
            }
        }

        float tm0 = NEGBIG, tm1 = NEGBIG;
#pragma unroll
        for (int nb = 0; nb < 8; nb++) {
            tm0 = fmaxf(tm0, fmaxf(sacc[nb][0], sacc[nb][1]));
            tm1 = fmaxf(tm1, fmaxf(sacc[nb][2], sacc[nb][3]));
        }
        tm0 = fmaxf(tm0, __shfl_xor_sync(0xffffffffu, tm0, 1));
        tm0 = fmaxf(tm0, __shfl_xor_sync(0xffffffffu, tm0, 2));
        tm1 = fmaxf(tm1, __shfl_xor_sync(0xffffffffu, tm1, 1));
        tm1 = fmaxf(tm1, __shfl_xor_sync(0xffffffffu, tm1, 2));

        float mn0 = fmaxf(m0, tm0);
        float mn1 = fmaxf(m1, tm1);
        float corr0 = ex2f(m0 - mn0);
        float corr1 = ex2f(m1 - mn1);
        float rs0 = 0.0f, rs1 = 0.0f;
#pragma unroll
        for (int nb = 0; nb < 8; nb++) {
            sacc[nb][0] = ex2f(sacc[nb][0] - mn0);
            sacc[nb][1] = ex2f(sacc[nb][1] - mn0);
            sacc[nb][2] = ex2f(sacc[nb][2] - mn1);
            sacc[nb][3] = ex2f(sacc[nb][3] - mn1);
            rs0 += sacc[nb][0] + sacc[nb][1];
            rs1 += sacc[nb][2] + sacc[nb][3];
        }
        rs0 += __shfl_xor_sync(0xffffffffu, rs0, 1);
        rs0 += __shfl_xor_sync(0xffffffffu, rs0, 2);
        rs1 += __shfl_xor_sync(0xffffffffu, rs1, 1);
        rs1 += __shfl_xor_sync(0xffffffffu, rs1, 2);

        l0 = l0 * corr0 + rs0;
        l1 = l1 * corr1 + rs1;
        m0 = mn0;
        m1 = mn1;
#pragma unroll
        for (int db = 0; db < 8; db++) {
            oacc[db][0] *= corr0;
            oacc[db][1] *= corr0;
            oacc[db][2] *= corr1;
            oacc[db][3] *= corr1;
        }

#pragma unroll
        for (int ks = 0; ks < 4; ks++) {
            uint32_t p16[4];
            p16[0] = h2u(__floats2half2_rn(sacc[2 * ks][0], sacc[2 * ks][1]));
            p16[1] = h2u(__floats2half2_rn(sacc[2 * ks][2], sacc[2 * ks][3]));
            p16[2] = h2u(__floats2half2_rn(sacc[2 * ks + 1][0], sacc[2 * ks + 1][1]));
            p16[3] = h2u(__floats2half2_rn(sacc[2 * ks + 1][2], sacc[2 * ks + 1][3]));
            const uint32_t ko = (uint32_t)(ks * 32);
#pragma unroll
            for (int dbp = 0; dbp < 4; dbp++) {
                const uint32_t ba = bufa + (uint32_t)(dbp * 16 * FRS) + ko;
                uint32_t v0, v1, v2, v3;
                ldsm_x4(v0, v1, v2, v3, ba + OFF_VT);
                mma_fp16(oacc[2 * dbp], p16[0], p16[1], p16[2], p16[3], v0, v1);
                mma_fp16(oacc[2 * dbp + 1], p16[0], p16[1], p16[2], p16[3], v2, v3);
            }
        }
    }

    float inv0 = 1.0f / l0;
    float inv1 = 1.0f / l1;
    int b = bh >> 4;
    int h = bh & 15;
    const size_t rb = (size_t)((b * TSEQ + q0) >> 4) + w;
#pragma unroll
    for (int dbp = 0; dbp < 4; dbp++) {
        int cb = h * 4 + dbp;
        uint4 v;
        v.x = h2u(__floats2half2_rn(oacc[2 * dbp][0] * inv0, oacc[2 * dbp][1] * inv0));
        v.y = h2u(__floats2half2_rn(oacc[2 * dbp][2] * inv1, oacc[2 * dbp][3] * inv1));
        v.z = h2u(__floats2half2_rn(oacc[2 * dbp + 1][0] * inv0, oacc[2 * dbp + 1][1] * inv0));
        v.w = h2u(__floats2half2_rn(oacc[2 * dbp + 1][2] * inv1, oacc[2 * dbp + 1][3] * inv1));
        g_yf[(rb * 64 + cb) * 32 + lane] = v;
    }
}

// ---------------------------------------------------------------------------
// Launch
// ---------------------------------------------------------------------------
extern "C" void kernel_launch(void* const* d_in, const int* in_sizes, int n_in,
                              void* d_out, int out_size) {
    const float* x      = (const float*)d_in[0];
    const float* w_attn = (const float*)d_in[1];
    const float* b_attn = (const float*)d_in[2];
    const float* w_proj = (const float*)d_in[3];
    const float* b_proj = (const float*)d_in[4];
    float* out = (float*)d_out;

    uint4 *xf, *waf, *wpf, *yf;
    float2* rope;
    __half *qf, *kf, *vt;
    cudaGetSymbolAddress((void**)&xf, g_xf);
    cudaGetSymbolAddress((void**)&waf, g_waf);
    cudaGetSymbolAddress((void**)&wpf, g_wpf);
    cudaGetSymbolAddress((void**)&yf, g_yf);
    cudaGetSymbolAddress((void**)&qf, g_qf);
    cudaGetSymbolAddress((void**)&kf, g_kf);
    cudaGetSymbolAddress((void**)&vt, g_vt);
    cudaGetSymbolAddress((void**)&rope, g_rope);

    cudaFuncSetAttribute(gemm_fp16_kernel,
                         cudaFuncAttributeMaxDynamicSharedMemorySize,
                         GEMM_SMEM_BYTES);
    cudaFuncSetAttribute(flash_mma_kernel,
                         cudaFuncAttributeMaxDynamicSharedMemorySize,
                         FLASH_SMEM_BYTES);

    build_rope_kernel<<<(TSEQ * 32 + 255) / 256, 256>>>(rope);

    afrag16_kernel<<<(MROWS / 16) * (CDIM / 16) * 32 / 256, 256>>>(x, xf, CDIM);
    bfrag16_kernel<<<(CDIM / 16) * (QKVCOLS / 16) * 32 / 256, 256>>>(w_attn, waf, QKVCOLS);
    bfrag16_kernel<<<(CDIM / 16) * (CDIM / 16) * 32 / 256, 256>>>(w_proj, wpf, CDIM);

    // QKV GEMM, persistent (768 tiles on 296 CTAs), fused RoPE/scatter epilogue
    gemm_fp16_kernel<<<296, 256, GEMM_SMEM_BYTES>>>(
        xf, waf, b_attn, out /*unused*/, MROWS, QKVCOLS, CDIM, 1);

    // Flash attention (writes yf as fp16 A-fragments)
    flash_mma_kernel<<<dim3(TSEQ / 64, BSZ * NHEAD), 128, FLASH_SMEM_BYTES>>>(
        qf, kf, vt);

    // Output projection (256 tiles -> single wave)
    gemm_fp16_kernel<<<256, 256, GEMM_SMEM_BYTES>>>(
        yf, wpf, b_proj, out, MROWS, CDIM, CDIM, 0);
}